// round 3
// baseline (speedup 1.0000x reference)
#include <cuda_runtime.h>
#include <math.h>

// ---------------------------------------------------------------------------
// MemDecoder: 5 grouped convs (8x8 spatial) -> feat[2048]; then per-pixel MLP
// over 65536 coords: w1 (feat part folded into constant c1), 8x additive
// coupling (512/512), w2 (grid part split out), 8x additive coupling (256/256),
// w3 -> sigmoid -> *1.1 - 0.05.  All fp32.
// ---------------------------------------------------------------------------

#define NP 65536

// scratch (device globals; zero-initialized at module load)
__device__ float g_grid[NP * 32];
__device__ float g_mid[NP * 1024];
__device__ float g_h2[NP * 512];
__device__ float g_feat[2048];
__device__ float g_c1[1024];
__device__ float g_cva[768 * 64];
__device__ float g_cvb[768 * 64];
__device__ float g_m1wf[8 * 512 * 512];
__device__ float g_m1wg[8 * 512 * 512];
__device__ float g_m2wf[8 * 256 * 256];
__device__ float g_m2wg[8 * 256 * 256];

// ---------------------------------------------------------------------------
// Positional grid: g[m, 2k] = sin(r_i * 2^(k/2)), g[m, 2k+1] = sin(r_j * 2^(k/2))
// m = i*256 + j, r_t = (t-128)*pi/256. Computed in double for accuracy.
// ---------------------------------------------------------------------------
__global__ void k_grid() {
    int m = blockIdx.x * blockDim.x + threadIdx.x;
    int i = m >> 8, j = m & 255;
    double ri = (double)(i - 128) * (3.14159265358979323846 / 256.0);
    double rj = (double)(j - 128) * (3.14159265358979323846 / 256.0);
#pragma unroll
    for (int k = 0; k < 16; k++) {
        double s = exp2((double)k * 0.5);
        g_grid[m * 32 + 2 * k]     = (float)sin(ri * s);
        g_grid[m * 32 + 2 * k + 1] = (float)sin(rj * s);
    }
}

// ---------------------------------------------------------------------------
// Grouped 3x3 conv + bias + leaky_relu(0.01). One block per output channel;
// 256 threads = npix pixels x nsl k-slices, smem reduce over slices.
// ---------------------------------------------------------------------------
__global__ void k_conv(const float* __restrict__ in, const float* __restrict__ w,
                       const float* __restrict__ bias, float* __restrict__ out,
                       int inH, int outH, int pad, int cinG, int coutPerGroup) {
    __shared__ float red[256];
    int oc = blockIdx.x;
    int grp = oc / coutPerGroup;
    int npix = outH * outH;
    int nsl = blockDim.x / npix;
    int t = threadIdx.x;
    int p = t % npix, sl = t / npix;
    float acc = 0.f;
    if (sl < nsl) {
        int oy = p / outH, ox = p % outH;
        const float* wrow = w + (size_t)oc * cinG * 9;
        const float* inb = in + (size_t)grp * cinG * inH * inH;
        for (int ci = sl; ci < cinG; ci += nsl) {
            const float* wp = wrow + ci * 9;
            const float* ip = inb + ci * inH * inH;
#pragma unroll
            for (int dy = 0; dy < 3; dy++) {
                int y = oy + dy - pad;
                if ((unsigned)y < (unsigned)inH) {
#pragma unroll
                    for (int dx = 0; dx < 3; dx++) {
                        int x = ox + dx - pad;
                        if ((unsigned)x < (unsigned)inH)
                            acc += wp[dy * 3 + dx] * ip[y * inH + x];
                    }
                }
            }
        }
    }
    red[t] = acc;
    __syncthreads();
    if (t < npix) {
        float s = 0.f;
        for (int q = 0; q < nsl; q++) s += red[p + q * npix];
        s += bias[oc];
        out[(size_t)oc * npix + p] = s > 0.f ? s : 0.01f * s;
    }
}

// c1[n] = w1[n, 32:2080] . feat + b1[n]
__global__ void k_c1(const float* __restrict__ w1, const float* __restrict__ b1) {
    int n = blockIdx.x * blockDim.x + threadIdx.x;
    if (n >= 1024) return;
    const float* wr = w1 + (size_t)n * 2080 + 32;
    float acc = b1[n];
#pragma unroll 4
    for (int k = 0; k < 2048; k++) acc += wr[k] * g_feat[k];
    g_c1[n] = acc;
}

// weight-norm: out[r, :] = v[r, :] * g[r] / ||v[r, :]||
__global__ void k_wnorm(const float* __restrict__ v, const float* __restrict__ gg,
                        float* __restrict__ out, int K) {
    __shared__ float sm[128];
    int r = blockIdx.x;
    const float* vr = v + (size_t)r * K;
    float ss = 0.f;
    for (int i = threadIdx.x; i < K; i += blockDim.x) { float x = vr[i]; ss += x * x; }
    sm[threadIdx.x] = ss;
    __syncthreads();
    for (int s = 64; s > 0; s >>= 1) {
        if (threadIdx.x < s) sm[threadIdx.x] += sm[threadIdx.x + s];
        __syncthreads();
    }
    float scale = gg[r] / sqrtf(sm[0]);
    for (int i = threadIdx.x; i < K; i += blockDim.x) out[(size_t)r * K + i] = vr[i] * scale;
}

// ---------------------------------------------------------------------------
// Generic fp32 GEMM: D[m,n] = epi( sum_k A[m,k] * B[n,k] )
// BM=128, BN=64, BK=16, 256 threads, 8x4 per-thread microtile.
// epi: + bias[n] (HAS_BIAS), + addIn[m,n] (ADD_IN, inside lrelu),
//      lrelu (LRELU), + res[m,n] (RES, outside lrelu).
// Requires M%128==0, N%64==0, K%16==0 (true for all uses here).
// ---------------------------------------------------------------------------
template <bool HAS_BIAS, bool ADD_IN, bool LRELU, bool RES>
__global__ void __launch_bounds__(256) k_gemm(
    int Nout, int K,
    const float* __restrict__ A, int lda,
    const float* __restrict__ B, int ldb,
    const float* __restrict__ bias,
    const float* __restrict__ addIn, int ldAdd,
    const float* __restrict__ res, int ldRes,
    float* __restrict__ D, int ldd) {
    __shared__ float As[16 * 128];
    __shared__ float Bs[16 * 64];
    int t = threadIdx.x;
    int tx = t & 15, ty = t >> 4;
    int m0 = blockIdx.y * 128, n0 = blockIdx.x * 64;
    float acc[8][4];
#pragma unroll
    for (int i = 0; i < 8; i++)
#pragma unroll
        for (int j = 0; j < 4; j++) acc[i][j] = 0.f;

    for (int k0 = 0; k0 < K; k0 += 16) {
#pragma unroll
        for (int u = 0; u < 2; u++) {
            int v = t + u * 256;
            int r = v >> 2, c = v & 3;
            float4 f = *(const float4*)(A + (size_t)(m0 + r) * lda + k0 + c * 4);
            As[(c * 4 + 0) * 128 + r] = f.x;
            As[(c * 4 + 1) * 128 + r] = f.y;
            As[(c * 4 + 2) * 128 + r] = f.z;
            As[(c * 4 + 3) * 128 + r] = f.w;
        }
        {
            int r = t >> 2, c = t & 3;
            float4 f = *(const float4*)(B + (size_t)(n0 + r) * ldb + k0 + c * 4);
            Bs[(c * 4 + 0) * 64 + r] = f.x;
            Bs[(c * 4 + 1) * 64 + r] = f.y;
            Bs[(c * 4 + 2) * 64 + r] = f.z;
            Bs[(c * 4 + 3) * 64 + r] = f.w;
        }
        __syncthreads();
#pragma unroll
        for (int kk = 0; kk < 16; kk++) {
            float a[8], b[4];
#pragma unroll
            for (int i = 0; i < 8; i++) a[i] = As[kk * 128 + ty * 8 + i];
#pragma unroll
            for (int j = 0; j < 4; j++) b[j] = Bs[kk * 64 + tx * 4 + j];
#pragma unroll
            for (int i = 0; i < 8; i++)
#pragma unroll
                for (int j = 0; j < 4; j++) acc[i][j] += a[i] * b[j];
        }
        __syncthreads();
    }

#pragma unroll
    for (int i = 0; i < 8; i++) {
        size_t m = (size_t)m0 + ty * 8 + i;
#pragma unroll
        for (int j = 0; j < 4; j++) {
            int n = n0 + tx * 4 + j;
            float v = acc[i][j];
            if (HAS_BIAS) v += bias[n];
            if (ADD_IN) v += addIn[m * ldAdd + n];
            if (LRELU) v = v > 0.f ? v : 0.01f * v;
            if (RES) v += res[m * ldRes + n];
            D[m * ldd + n] = v;
        }
    }
}

// final: out[c, p] = sigmoid(h2[p] . w3[c] + b3[c]) * 1.1 - 0.05
__global__ void k_out(const float* __restrict__ w3, const float* __restrict__ b3,
                      float* __restrict__ out) {
    __shared__ float ws[3 * 512];
    for (int i = threadIdx.x; i < 1536; i += blockDim.x) ws[i] = w3[i];
    __syncthreads();
    int p = blockIdx.x * blockDim.x + threadIdx.x;
    const float* h = g_h2 + (size_t)p * 512;
    float a0 = b3[0], a1 = b3[1], a2 = b3[2];
#pragma unroll 4
    for (int k = 0; k < 512; k += 4) {
        float4 hv = *(const float4*)(h + k);
        a0 += hv.x * ws[k] + hv.y * ws[k + 1] + hv.z * ws[k + 2] + hv.w * ws[k + 3];
        a1 += hv.x * ws[512 + k] + hv.y * ws[512 + k + 1] + hv.z * ws[512 + k + 2] + hv.w * ws[512 + k + 3];
        a2 += hv.x * ws[1024 + k] + hv.y * ws[1024 + k + 1] + hv.z * ws[1024 + k + 2] + hv.w * ws[1024 + k + 3];
    }
    out[p]           = 1.1f / (1.f + expf(-a0)) - 0.05f;
    out[NP + p]      = 1.1f / (1.f + expf(-a1)) - 0.05f;
    out[2 * NP + p]  = 1.1f / (1.f + expf(-a2)) - 0.05f;
}

extern "C" void kernel_launch(void* const* d_in, const int* in_sizes, int n_in,
                              void* d_out, int out_size) {
    const float* feature = (const float*)d_in[0];
    const float* cw1 = (const float*)d_in[1];  const float* cb1 = (const float*)d_in[2];
    const float* cw2 = (const float*)d_in[3];  const float* cb2 = (const float*)d_in[4];
    const float* cw3 = (const float*)d_in[5];  const float* cb3 = (const float*)d_in[6];
    const float* cw4 = (const float*)d_in[7];  const float* cb4 = (const float*)d_in[8];
    const float* cw5 = (const float*)d_in[9];  const float* cb5 = (const float*)d_in[10];
    const float* w1  = (const float*)d_in[11]; const float* b1  = (const float*)d_in[12];
    const float* m1_vf = (const float*)d_in[13]; const float* m1_gf = (const float*)d_in[14];
    const float* m1_bf = (const float*)d_in[15];
    const float* m1_vg = (const float*)d_in[16]; const float* m1_gg = (const float*)d_in[17];
    const float* m1_bg = (const float*)d_in[18];
    const float* w2  = (const float*)d_in[19]; const float* b2  = (const float*)d_in[20];
    const float* m2_vf = (const float*)d_in[21]; const float* m2_gf = (const float*)d_in[22];
    const float* m2_bf = (const float*)d_in[23];
    const float* m2_vg = (const float*)d_in[24]; const float* m2_gg = (const float*)d_in[25];
    const float* m2_bg = (const float*)d_in[26];
    const float* w3  = (const float*)d_in[27]; const float* b3  = (const float*)d_in[28];
    float* out = (float*)d_out;

    float *p_grid, *p_mid, *p_h2, *p_cva, *p_cvb, *p_feat, *p_c1;
    float *p_m1wf, *p_m1wg, *p_m2wf, *p_m2wg;
    cudaGetSymbolAddress((void**)&p_grid, g_grid);
    cudaGetSymbolAddress((void**)&p_mid,  g_mid);
    cudaGetSymbolAddress((void**)&p_h2,   g_h2);
    cudaGetSymbolAddress((void**)&p_cva,  g_cva);
    cudaGetSymbolAddress((void**)&p_cvb,  g_cvb);
    cudaGetSymbolAddress((void**)&p_feat, g_feat);
    cudaGetSymbolAddress((void**)&p_c1,   g_c1);
    cudaGetSymbolAddress((void**)&p_m1wf, g_m1wf);
    cudaGetSymbolAddress((void**)&p_m1wg, g_m1wg);
    cudaGetSymbolAddress((void**)&p_m2wf, g_m2wf);
    cudaGetSymbolAddress((void**)&p_m2wg, g_m2wg);

    // --- independent prep ---
    k_grid<<<NP / 256, 256>>>();
    k_wnorm<<<4096, 128>>>(m1_vf, m1_gf, p_m1wf, 512);
    k_wnorm<<<4096, 128>>>(m1_vg, m1_gg, p_m1wg, 512);
    k_wnorm<<<2048, 128>>>(m2_vf, m2_gf, p_m2wf, 256);
    k_wnorm<<<2048, 128>>>(m2_vg, m2_gg, p_m2wg, 256);

    // --- conv chain (tiny) ---
    k_conv<<<768, 256>>>(feature, cw1, cb1, p_cva, 8, 8, 1, 448, 192);
    k_conv<<<768, 256>>>(p_cva,  cw2, cb2, p_cvb, 8, 8, 1, 256, 256);
    k_conv<<<768, 256>>>(p_cvb,  cw3, cb3, p_cva, 8, 8, 1, 384, 384);
    k_conv<<<768, 256>>>(p_cva,  cw4, cb4, p_cvb, 8, 6, 0, 256, 256);
    k_conv<<<128, 256>>>(p_cvb,  cw5, cb5, p_feat, 6, 4, 0, 768, 128);
    k_c1<<<4, 256>>>(w1, b1);

    // --- mid0 = lrelu(grid @ w1[:, :32].T + c1) : [N, 1024] ---
    k_gemm<true, false, true, false><<<dim3(1024 / 64, NP / 128), 256>>>(
        1024, 32, p_grid, 32, w1, 2080, p_c1, nullptr, 0, nullptr, 0, p_mid, 1024);

    // --- mem stack 1: 8 additive-coupling steps on [N, 512|512] ---
    for (int l = 0; l < 8; l++) {
        // y1 = h1 + lrelu(Wf . h2 + bf)   (writes cols 0..511)
        k_gemm<true, false, true, true><<<dim3(8, NP / 128), 256>>>(
            512, 512, p_mid + 512, 1024, p_m1wf + (size_t)l * 512 * 512, 512,
            m1_bf + l * 512, nullptr, 0, p_mid, 1024, p_mid, 1024);
        // y2 = h2 + lrelu(Wg . y1 + bg)   (writes cols 512..1023)
        k_gemm<true, false, true, true><<<dim3(8, NP / 128), 256>>>(
            512, 512, p_mid, 1024, p_m1wg + (size_t)l * 512 * 512, 512,
            m1_bg + l * 512, nullptr, 0, p_mid + 512, 1024, p_mid + 512, 1024);
    }

    // --- h2 = lrelu(grid @ w2[:, :32].T + mid @ w2[:, 32:].T + b2) : [N, 512] ---
    k_gemm<false, false, false, false><<<dim3(8, NP / 128), 256>>>(
        512, 32, p_grid, 32, w2, 1056, nullptr, nullptr, 0, nullptr, 0, p_h2, 512);
    k_gemm<true, true, true, false><<<dim3(8, NP / 128), 256>>>(
        512, 1024, p_mid, 1024, w2 + 32, 1056, b2, p_h2, 512, nullptr, 0, p_h2, 512);

    // --- mem stack 2: 8 steps on [N, 256|256] ---
    for (int l = 0; l < 8; l++) {
        k_gemm<true, false, true, true><<<dim3(4, NP / 128), 256>>>(
            256, 256, p_h2 + 256, 512, p_m2wf + (size_t)l * 256 * 256, 256,
            m2_bf + l * 256, nullptr, 0, p_h2, 512, p_h2, 512);
        k_gemm<true, false, true, true><<<dim3(4, NP / 128), 256>>>(
            256, 256, p_h2, 512, p_m2wg + (size_t)l * 256 * 256, 256,
            m2_bg + l * 256, nullptr, 0, p_h2 + 256, 512, p_h2 + 256, 512);
    }

    // --- output ---
    k_out<<<NP / 256, 256>>>(w3, b3, out);
}

// round 7
// speedup vs baseline: 1.6889x; 1.6889x over previous
#include <cuda_runtime.h>
#include <cuda_bf16.h>
#include <cstdint>
#include <math.h>

// ===========================================================================
// MemDecoder via mma.sync bf16 (baseline sm_103-compatible; no tcgen05).
// Activations/weights as (hi,lo) bf16 planes; 3-product error-compensated
// GEMMs (AH*BH + AH*BL + AL*BH) with fp32 accumulation.
// Tile: BM=128, BN=128, BK=64, 8 warps, cp.async double buffer.
// ===========================================================================

#define NP 65536

// ---------------- device scratch ------------------------------------------
__device__ float g_grid[NP * 32];
__device__ float g_tmp[NP * 512];
__device__ __nv_bfloat16 g_midH[NP * 1024];
__device__ __nv_bfloat16 g_midL[NP * 1024];
__device__ __nv_bfloat16 g_h2H[NP * 512];
__device__ __nv_bfloat16 g_h2L[NP * 512];
__device__ float g_feat[2048];
__device__ float g_c1[1024];
__device__ float g_cva[768 * 64];
__device__ float g_cvb[768 * 64];
__device__ __nv_bfloat16 g_m1wfH[8 * 512 * 512];
__device__ __nv_bfloat16 g_m1wfL[8 * 512 * 512];
__device__ __nv_bfloat16 g_m1wgH[8 * 512 * 512];
__device__ __nv_bfloat16 g_m1wgL[8 * 512 * 512];
__device__ __nv_bfloat16 g_m2wfH[8 * 256 * 256];
__device__ __nv_bfloat16 g_m2wfL[8 * 256 * 256];
__device__ __nv_bfloat16 g_m2wgH[8 * 256 * 256];
__device__ __nv_bfloat16 g_m2wgL[8 * 256 * 256];
__device__ __nv_bfloat16 g_w2H[512 * 1024];
__device__ __nv_bfloat16 g_w2L[512 * 1024];

__device__ __forceinline__ void split2(float v, __nv_bfloat16& h, __nv_bfloat16& l) {
    h = __float2bfloat16(v);
    l = __float2bfloat16(v - __bfloat162float(h));
}

__device__ __forceinline__ uint32_t smem_to_u32(const void* p) {
    uint32_t a;
    asm("{ .reg .u64 t; cvta.to.shared.u64 t, %1; cvt.u32.u64 %0, t; }" : "=r"(a) : "l"(p));
    return a;
}

#define LDSM_X4(r0, r1, r2, r3, addr) \
    asm volatile("ldmatrix.sync.aligned.m8n8.x4.shared.b16 {%0,%1,%2,%3}, [%4];" \
                 : "=r"(r0), "=r"(r1), "=r"(r2), "=r"(r3) : "r"(addr))
#define LDSM_X2(r0, r1, addr) \
    asm volatile("ldmatrix.sync.aligned.m8n8.x2.shared.b16 {%0,%1}, [%2];" \
                 : "=r"(r0), "=r"(r1) : "r"(addr))

__device__ __forceinline__ void mma16816(float* c, const uint32_t* a, const uint32_t* b) {
    asm volatile(
        "mma.sync.aligned.m16n8k16.row.col.f32.bf16.bf16.f32 "
        "{%0,%1,%2,%3}, {%4,%5,%6,%7}, {%8,%9}, {%0,%1,%2,%3};"
        : "+f"(c[0]), "+f"(c[1]), "+f"(c[2]), "+f"(c[3])
        : "r"(a[0]), "r"(a[1]), "r"(a[2]), "r"(a[3]), "r"(b[0]), "r"(b[1]));
}

// ---------------- small prep kernels --------------------------------------
__global__ void k_grid() {
    int m = blockIdx.x * blockDim.x + threadIdx.x;
    int i = m >> 8, j = m & 255;
    double ri = (double)(i - 128) * (3.14159265358979323846 / 256.0);
    double rj = (double)(j - 128) * (3.14159265358979323846 / 256.0);
#pragma unroll
    for (int k = 0; k < 16; k++) {
        double s = exp2((double)k * 0.5);
        g_grid[m * 32 + 2 * k]     = (float)sin(ri * s);
        g_grid[m * 32 + 2 * k + 1] = (float)sin(rj * s);
    }
}

__global__ void k_conv(const float* __restrict__ in, const float* __restrict__ w,
                       const float* __restrict__ bias, float* __restrict__ out,
                       int inH, int outH, int pad, int cinG, int coutPerGroup) {
    __shared__ float red[256];
    int oc = blockIdx.x;
    int grp = oc / coutPerGroup;
    int npix = outH * outH;
    int nsl = blockDim.x / npix;
    int t = threadIdx.x;
    int p = t % npix, sl = t / npix;
    float acc = 0.f;
    if (sl < nsl) {
        int oy = p / outH, ox = p % outH;
        const float* wrow = w + (size_t)oc * cinG * 9;
        const float* inb = in + (size_t)grp * cinG * inH * inH;
        for (int ci = sl; ci < cinG; ci += nsl) {
            const float* wp = wrow + ci * 9;
            const float* ip = inb + ci * inH * inH;
#pragma unroll
            for (int dy = 0; dy < 3; dy++) {
                int y = oy + dy - pad;
                if ((unsigned)y < (unsigned)inH) {
#pragma unroll
                    for (int dx = 0; dx < 3; dx++) {
                        int x = ox + dx - pad;
                        if ((unsigned)x < (unsigned)inH)
                            acc += wp[dy * 3 + dx] * ip[y * inH + x];
                    }
                }
            }
        }
    }
    red[t] = acc;
    __syncthreads();
    if (t < npix) {
        float s = 0.f;
        for (int q = 0; q < nsl; q++) s += red[p + q * npix];
        s += bias[oc];
        out[(size_t)oc * npix + p] = s > 0.f ? s : 0.01f * s;
    }
}

__global__ void k_c1(const float* __restrict__ w1, const float* __restrict__ b1) {
    int n = blockIdx.x * blockDim.x + threadIdx.x;
    if (n >= 1024) return;
    const float* wr = w1 + (size_t)n * 2080 + 32;
    float acc = b1[n];
#pragma unroll 4
    for (int k = 0; k < 2048; k++) acc += wr[k] * g_feat[k];
    g_c1[n] = acc;
}

__global__ void k_wnorm(const float* __restrict__ v, const float* __restrict__ gg,
                        __nv_bfloat16* __restrict__ H, __nv_bfloat16* __restrict__ L, int K) {
    __shared__ float sm[128];
    int r = blockIdx.x;
    const float* vr = v + (size_t)r * K;
    float ss = 0.f;
    for (int i = threadIdx.x; i < K; i += blockDim.x) { float x = vr[i]; ss += x * x; }
    sm[threadIdx.x] = ss;
    __syncthreads();
    for (int s = 64; s > 0; s >>= 1) {
        if (threadIdx.x < s) sm[threadIdx.x] += sm[threadIdx.x + s];
        __syncthreads();
    }
    float scale = gg[r] / sqrtf(sm[0]);
    for (int i = threadIdx.x; i < K; i += blockDim.x) {
        float w = vr[i] * scale;
        split2(w, H[(size_t)r * K + i], L[(size_t)r * K + i]);
    }
}

__global__ void k_split_w2(const float* __restrict__ w2) {
    int r = blockIdx.x;
    const float* src = w2 + (size_t)r * 1056 + 32;
    for (int i = threadIdx.x; i < 1024; i += blockDim.x)
        split2(src[i], g_w2H[(size_t)r * 1024 + i], g_w2L[(size_t)r * 1024 + i]);
}

// ---------------- fp32 SIMT GEMM for tiny-K prologues ----------------------
// PLANES: write hi/lo bf16 planes; else write fp32 D.
template <bool HAS_BIAS, bool LRELU, bool PLANES>
__global__ void __launch_bounds__(256) k_gemm32(
    int K,
    const float* __restrict__ A, int lda,
    const float* __restrict__ B, int ldb,
    const float* __restrict__ bias,
    float* __restrict__ D,
    __nv_bfloat16* __restrict__ DH, __nv_bfloat16* __restrict__ DL, int ldd) {
    __shared__ float As[16 * 128];
    __shared__ float Bs[16 * 64];
    int t = threadIdx.x;
    int tx = t & 15, ty = t >> 4;
    int m0 = blockIdx.y * 128, n0 = blockIdx.x * 64;
    float acc[8][4];
#pragma unroll
    for (int i = 0; i < 8; i++)
#pragma unroll
        for (int j = 0; j < 4; j++) acc[i][j] = 0.f;
    for (int k0 = 0; k0 < K; k0 += 16) {
#pragma unroll
        for (int u = 0; u < 2; u++) {
            int v = t + u * 256;
            int r = v >> 2, c = v & 3;
            float4 f = *(const float4*)(A + (size_t)(m0 + r) * lda + k0 + c * 4);
            As[(c * 4 + 0) * 128 + r] = f.x;
            As[(c * 4 + 1) * 128 + r] = f.y;
            As[(c * 4 + 2) * 128 + r] = f.z;
            As[(c * 4 + 3) * 128 + r] = f.w;
        }
        {
            int r = t >> 2, c = t & 3;
            float4 f = *(const float4*)(B + (size_t)(n0 + r) * ldb + k0 + c * 4);
            Bs[(c * 4 + 0) * 64 + r] = f.x;
            Bs[(c * 4 + 1) * 64 + r] = f.y;
            Bs[(c * 4 + 2) * 64 + r] = f.z;
            Bs[(c * 4 + 3) * 64 + r] = f.w;
        }
        __syncthreads();
#pragma unroll
        for (int kk = 0; kk < 16; kk++) {
            float a[8], b[4];
#pragma unroll
            for (int i = 0; i < 8; i++) a[i] = As[kk * 128 + ty * 8 + i];
#pragma unroll
            for (int j = 0; j < 4; j++) b[j] = Bs[kk * 64 + tx * 4 + j];
#pragma unroll
            for (int i = 0; i < 8; i++)
#pragma unroll
                for (int j = 0; j < 4; j++) acc[i][j] += a[i] * b[j];
        }
        __syncthreads();
    }
#pragma unroll
    for (int i = 0; i < 8; i++) {
        size_t m = (size_t)m0 + ty * 8 + i;
#pragma unroll
        for (int j = 0; j < 4; j++) {
            int n = n0 + tx * 4 + j;
            float v = acc[i][j];
            if (HAS_BIAS) v += bias[n];
            if (LRELU) v = v > 0.f ? v : 0.01f * v;
            if (PLANES) split2(v, DH[m * ldd + n], DL[m * ldd + n]);
            else D[m * ldd + n] = v;
        }
    }
}

// ---------------- mma.sync GEMM -------------------------------------------
// D[m0..+127, n0..+127] = epi( (AH+AL)[128,K] @ (BH+BL)[128,K]^T )
// epi: +bias (HAS_BIAS), +add fp32 (ADD_IN), lrelu (always), +res=out planes
// (RES); writes (hi,lo) bf16 planes.
#define ROWB 144                    // padded row stride (bytes) for 64 bf16
#define PLANE (128 * ROWB)          // 18432 B
#define STAGE (4 * PLANE)           // AH | AL | BH | BL  = 73728 B
#define SMEM_MMA (2 * STAGE)        // 147456 B

template <bool ADD_IN, bool RES, bool HAS_BIAS>
__global__ void __launch_bounds__(256) k_mma(
    int K,
    const __nv_bfloat16* __restrict__ AH, const __nv_bfloat16* __restrict__ AL, int lda,
    const __nv_bfloat16* __restrict__ BH, const __nv_bfloat16* __restrict__ BL, int ldb,
    const float* __restrict__ bias,
    const float* __restrict__ add, int ldadd,
    __nv_bfloat16* __restrict__ outH, __nv_bfloat16* __restrict__ outL, int ldd) {
    extern __shared__ char smem[];
    uint32_t sb = smem_to_u32(smem);
    const int tid = threadIdx.x;
    const int lane = tid & 31, w = tid >> 5;
    const int wm = w & 1, wn = w >> 1;   // 2 M-warps x 4 N-warps
    const int m0 = blockIdx.y * 128, n0 = blockIdx.x * 128;
    const int CH = K >> 6;

    float acc[4][4][4];
#pragma unroll
    for (int a = 0; a < 4; a++)
#pragma unroll
        for (int b = 0; b < 4; b++)
#pragma unroll
            for (int c = 0; c < 4; c++) acc[a][b][c] = 0.f;

    // ---- async copy of one K-chunk (64 cols, 4 planes) ----
    auto issue = [&](int c) {
        uint32_t st = sb + (uint32_t)(c & 1) * STAGE;
        int k0 = c << 6;
#pragma unroll
        for (int i = 0; i < 16; i++) {
            const int plane = i >> 2;                       // compile-time per i
            int v = (i & 3) * 256 + tid;
            int row = v >> 3, cc = v & 7;
            const __nv_bfloat16* src;
            if (plane == 0)      src = AH + (size_t)(m0 + row) * lda + k0 + cc * 8;
            else if (plane == 1) src = AL + (size_t)(m0 + row) * lda + k0 + cc * 8;
            else if (plane == 2) src = BH + (size_t)(n0 + row) * ldb + k0 + cc * 8;
            else                 src = BL + (size_t)(n0 + row) * ldb + k0 + cc * 8;
            uint32_t dst = st + (uint32_t)plane * PLANE + (uint32_t)(row * ROWB + cc * 16);
            asm volatile("cp.async.cg.shared.global [%0], [%1], 16;" :: "r"(dst), "l"(src));
        }
        asm volatile("cp.async.commit_group;" ::: "memory");
    };

    issue(0);
    for (int c = 0; c < CH; c++) {
        if (c + 1 < CH) {
            issue(c + 1);
            asm volatile("cp.async.wait_group 1;" ::: "memory");
        } else {
            asm volatile("cp.async.wait_group 0;" ::: "memory");
        }
        __syncthreads();

        uint32_t st = sb + (uint32_t)(c & 1) * STAGE;
#pragma unroll
        for (int ks = 0; ks < 4; ks++) {
            uint32_t aH[4][4], aL[4][4], bH[4][2], bL[4][2];
            {
                int arow = wm * 64 + (lane & 15);
                int acol = (ks * 16 + ((lane >> 4) << 3)) * 2;
#pragma unroll
                for (int mt = 0; mt < 4; mt++) {
                    uint32_t ad = st + (uint32_t)((arow + mt * 16) * ROWB + acol);
                    LDSM_X4(aH[mt][0], aH[mt][1], aH[mt][2], aH[mt][3], ad);
                    LDSM_X4(aL[mt][0], aL[mt][1], aL[mt][2], aL[mt][3], ad + PLANE);
                }
            }
            {
                int brow = wn * 32 + (lane & 7);
                int bcol = (ks * 16 + (((lane >> 3) & 1) << 3)) * 2;
#pragma unroll
                for (int nt = 0; nt < 4; nt++) {
                    uint32_t bd = st + 2 * PLANE + (uint32_t)((brow + nt * 8) * ROWB + bcol);
                    LDSM_X2(bH[nt][0], bH[nt][1], bd);
                    LDSM_X2(bL[nt][0], bL[nt][1], bd + PLANE);
                }
            }
#pragma unroll
            for (int mt = 0; mt < 4; mt++)
#pragma unroll
                for (int nt = 0; nt < 4; nt++) {
                    mma16816(acc[mt][nt], aH[mt], bH[nt]);
                    mma16816(acc[mt][nt], aH[mt], bL[nt]);
                    mma16816(acc[mt][nt], aL[mt], bH[nt]);
                }
        }
        __syncthreads();
    }

    // ---- epilogue ----
#pragma unroll
    for (int mt = 0; mt < 4; mt++)
#pragma unroll
        for (int nt = 0; nt < 4; nt++) {
            int n = n0 + wn * 32 + nt * 8 + (lane & 3) * 2;
            float bn0 = 0.f, bn1 = 0.f;
            if (HAS_BIAS) { bn0 = __ldg(bias + n); bn1 = __ldg(bias + n + 1); }
#pragma unroll
            for (int h = 0; h < 2; h++) {
                size_t m = (size_t)m0 + wm * 64 + mt * 16 + (lane >> 2) + h * 8;
                float v0 = acc[mt][nt][h * 2 + 0];
                float v1 = acc[mt][nt][h * 2 + 1];
                if (HAS_BIAS) { v0 += bn0; v1 += bn1; }
                if (ADD_IN) {
                    float2 f = *(const float2*)(add + m * ldadd + n);
                    v0 += f.x; v1 += f.y;
                }
                v0 = v0 > 0.f ? v0 : 0.01f * v0;
                v1 = v1 > 0.f ? v1 : 0.01f * v1;
                if (RES) {
                    __nv_bfloat162 rh = *(const __nv_bfloat162*)(outH + m * ldd + n);
                    __nv_bfloat162 rl = *(const __nv_bfloat162*)(outL + m * ldd + n);
                    v0 += __bfloat162float(rh.x) + __bfloat162float(rl.x);
                    v1 += __bfloat162float(rh.y) + __bfloat162float(rl.y);
                }
                __nv_bfloat16 h0, l0, h1, l1;
                split2(v0, h0, l0);
                split2(v1, h1, l1);
                __nv_bfloat162 hv; hv.x = h0; hv.y = h1;
                __nv_bfloat162 lv; lv.x = l0; lv.y = l1;
                *(__nv_bfloat162*)(outH + m * ldd + n) = hv;
                *(__nv_bfloat162*)(outL + m * ldd + n) = lv;
            }
        }
}

// ---------------- output kernel -------------------------------------------
__global__ void k_out(const float* __restrict__ w3, const float* __restrict__ b3,
                      float* __restrict__ out) {
    __shared__ float ws[3 * 512];
    for (int i = threadIdx.x; i < 1536; i += blockDim.x) ws[i] = w3[i];
    __syncthreads();
    int p = blockIdx.x * blockDim.x + threadIdx.x;
    const __nv_bfloat16* hH = g_h2H + (size_t)p * 512;
    const __nv_bfloat16* hL = g_h2L + (size_t)p * 512;
    float a0 = b3[0], a1 = b3[1], a2 = b3[2];
    for (int k = 0; k < 512; k += 8) {
        __nv_bfloat16 bh[8], bl[8];
        *(uint4*)bh = *(const uint4*)(hH + k);
        *(uint4*)bl = *(const uint4*)(hL + k);
#pragma unroll
        for (int q = 0; q < 8; q++) {
            float h = __bfloat162float(bh[q]) + __bfloat162float(bl[q]);
            a0 += h * ws[k + q];
            a1 += h * ws[512 + k + q];
            a2 += h * ws[1024 + k + q];
        }
    }
    out[p]          = 1.1f / (1.f + expf(-a0)) - 0.05f;
    out[NP + p]     = 1.1f / (1.f + expf(-a1)) - 0.05f;
    out[2 * NP + p] = 1.1f / (1.f + expf(-a2)) - 0.05f;
}

// ---------------- launch ---------------------------------------------------
extern "C" void kernel_launch(void* const* d_in, const int* in_sizes, int n_in,
                              void* d_out, int out_size) {
    const float* feature = (const float*)d_in[0];
    const float* cw1 = (const float*)d_in[1];  const float* cb1 = (const float*)d_in[2];
    const float* cw2 = (const float*)d_in[3];  const float* cb2 = (const float*)d_in[4];
    const float* cw3 = (const float*)d_in[5];  const float* cb3 = (const float*)d_in[6];
    const float* cw4 = (const float*)d_in[7];  const float* cb4 = (const float*)d_in[8];
    const float* cw5 = (const float*)d_in[9];  const float* cb5 = (const float*)d_in[10];
    const float* w1  = (const float*)d_in[11]; const float* b1  = (const float*)d_in[12];
    const float* m1_vf = (const float*)d_in[13]; const float* m1_gf = (const float*)d_in[14];
    const float* m1_bf = (const float*)d_in[15];
    const float* m1_vg = (const float*)d_in[16]; const float* m1_gg = (const float*)d_in[17];
    const float* m1_bg = (const float*)d_in[18];
    const float* w2  = (const float*)d_in[19]; const float* b2  = (const float*)d_in[20];
    const float* m2_vf = (const float*)d_in[21]; const float* m2_gf = (const float*)d_in[22];
    const float* m2_bf = (const float*)d_in[23];
    const float* m2_vg = (const float*)d_in[24]; const float* m2_gg = (const float*)d_in[25];
    const float* m2_bg = (const float*)d_in[26];
    const float* w3  = (const float*)d_in[27]; const float* b3  = (const float*)d_in[28];
    float* out = (float*)d_out;

    float *p_grid, *p_tmp, *p_feat, *p_c1, *p_cva, *p_cvb;
    __nv_bfloat16 *p_midH, *p_midL, *p_h2H, *p_h2L;
    __nv_bfloat16 *p_m1wfH, *p_m1wfL, *p_m1wgH, *p_m1wgL;
    __nv_bfloat16 *p_m2wfH, *p_m2wfL, *p_m2wgH, *p_m2wgL, *p_w2H, *p_w2L;
    cudaGetSymbolAddress((void**)&p_grid, g_grid);
    cudaGetSymbolAddress((void**)&p_tmp,  g_tmp);
    cudaGetSymbolAddress((void**)&p_feat, g_feat);
    cudaGetSymbolAddress((void**)&p_c1,   g_c1);
    cudaGetSymbolAddress((void**)&p_cva,  g_cva);
    cudaGetSymbolAddress((void**)&p_cvb,  g_cvb);
    cudaGetSymbolAddress((void**)&p_midH, g_midH);
    cudaGetSymbolAddress((void**)&p_midL, g_midL);
    cudaGetSymbolAddress((void**)&p_h2H,  g_h2H);
    cudaGetSymbolAddress((void**)&p_h2L,  g_h2L);
    cudaGetSymbolAddress((void**)&p_m1wfH, g_m1wfH);
    cudaGetSymbolAddress((void**)&p_m1wfL, g_m1wfL);
    cudaGetSymbolAddress((void**)&p_m1wgH, g_m1wgH);
    cudaGetSymbolAddress((void**)&p_m1wgL, g_m1wgL);
    cudaGetSymbolAddress((void**)&p_m2wfH, g_m2wfH);
    cudaGetSymbolAddress((void**)&p_m2wfL, g_m2wfL);
    cudaGetSymbolAddress((void**)&p_m2wgH, g_m2wgH);
    cudaGetSymbolAddress((void**)&p_m2wgL, g_m2wgL);
    cudaGetSymbolAddress((void**)&p_w2H, g_w2H);
    cudaGetSymbolAddress((void**)&p_w2L, g_w2L);

    cudaFuncSetAttribute((const void*)k_mma<false, true, true>,
                         cudaFuncAttributeMaxDynamicSharedMemorySize, SMEM_MMA);
    cudaFuncSetAttribute((const void*)k_mma<true, false, false>,
                         cudaFuncAttributeMaxDynamicSharedMemorySize, SMEM_MMA);

    // prep
    k_grid<<<NP / 256, 256>>>();
    k_wnorm<<<4096, 128>>>(m1_vf, m1_gf, p_m1wfH, p_m1wfL, 512);
    k_wnorm<<<4096, 128>>>(m1_vg, m1_gg, p_m1wgH, p_m1wgL, 512);
    k_wnorm<<<2048, 128>>>(m2_vf, m2_gf, p_m2wfH, p_m2wfL, 256);
    k_wnorm<<<2048, 128>>>(m2_vg, m2_gg, p_m2wgH, p_m2wgL, 256);
    k_split_w2<<<512, 256>>>(w2);

    // conv chain
    k_conv<<<768, 256>>>(feature, cw1, cb1, p_cva, 8, 8, 1, 448, 192);
    k_conv<<<768, 256>>>(p_cva,  cw2, cb2, p_cvb, 8, 8, 1, 256, 256);
    k_conv<<<768, 256>>>(p_cvb,  cw3, cb3, p_cva, 8, 8, 1, 384, 384);
    k_conv<<<768, 256>>>(p_cva,  cw4, cb4, p_cvb, 8, 6, 0, 256, 256);
    k_conv<<<128, 256>>>(p_cvb,  cw5, cb5, p_feat, 6, 4, 0, 768, 128);
    k_c1<<<4, 256>>>(w1, b1);

    // mid0 = lrelu(grid @ w1[:, :32]^T + c1) -> (hi,lo) planes directly
    k_gemm32<true, true, true><<<dim3(16, 512), 256>>>(
        32, p_grid, 32, w1, 2080, p_c1, nullptr, p_midH, p_midL, 1024);

    // mem stack 1: 16 coupling GEMMs [N, 512x512]
    for (int l = 0; l < 8; l++) {
        k_mma<false, true, true><<<dim3(4, 512), 256, SMEM_MMA>>>(
            512, p_midH + 512, p_midL + 512, 1024,
            p_m1wfH + (size_t)l * 262144, p_m1wfL + (size_t)l * 262144, 512,
            m1_bf + l * 512, nullptr, 0, p_midH, p_midL, 1024);
        k_mma<false, true, true><<<dim3(4, 512), 256, SMEM_MMA>>>(
            512, p_midH, p_midL, 1024,
            p_m1wgH + (size_t)l * 262144, p_m1wgL + (size_t)l * 262144, 512,
            m1_bg + l * 512, nullptr, 0, p_midH + 512, p_midL + 512, 1024);
    }

    // h2 = lrelu(grid @ w2[:, :32]^T + b2 + mid @ w2[:, 32:]^T)
    k_gemm32<true, false, false><<<dim3(8, 512), 256>>>(
        32, p_grid, 32, w2, 1056, b2, p_tmp, nullptr, nullptr, 512);
    k_mma<true, false, false><<<dim3(4, 512), 256, SMEM_MMA>>>(
        1024, p_midH, p_midL, 1024, p_w2H, p_w2L, 1024,
        nullptr, p_tmp, 512, p_h2H, p_h2L, 512);

    // mem stack 2: 16 coupling GEMMs [N, 256x256]
    for (int l = 0; l < 8; l++) {
        k_mma<false, true, true><<<dim3(2, 512), 256, SMEM_MMA>>>(
            256, p_h2H + 256, p_h2L + 256, 512,
            p_m2wfH + (size_t)l * 65536, p_m2wfL + (size_t)l * 65536, 256,
            m2_bf + l * 256, nullptr, 0, p_h2H, p_h2L, 512);
        k_mma<false, true, true><<<dim3(2, 512), 256, SMEM_MMA>>>(
            256, p_h2H, p_h2L, 512,
            p_m2wgH + (size_t)l * 65536, p_m2wgL + (size_t)l * 65536, 256,
            m2_bg + l * 256, nullptr, 0, p_h2H + 256, p_h2L + 256, 512);
    }

    k_out<<<NP / 256, 256>>>(w3, b3, out);
}